// round 16
// baseline (speedup 1.0000x reference)
#include <cuda_runtime.h>
#include <cuda_bf16.h>
#include <cstdint>

#define N_NODES 50000
#define N_EDGES 800000
#define F_IN    64
#define F_MID   128
#define GTILE   128
#define NTILES  ((N_NODES + GTILE - 1) / GTILE)   // 391
#define NBLK    148
#define NTHR    1024
#define TTOT    (NBLK * NTHR)                      // 151552

typedef unsigned long long u64;

// ---------------- scratch (device globals; no allocations) ----------------
__device__ int   g_deg_out[N_NODES];
__device__ int   g_deg_in [N_NODES];
__device__ float g_norm_src[N_NODES];
__device__ float g_norm_dst[N_NODES];
__device__ int   g_off [N_NODES];
__device__ int   g_alloc;
__device__ int   g_rank[N_EDGES];
__device__ int   g_esrc[N_EDGES];
__device__ float g_hs  [(size_t)N_NODES * F_IN];
__device__ float g_agg1[(size_t)N_NODES * F_IN];
__device__ float g_t2  [(size_t)N_NODES * F_IN];
__device__ unsigned g_barcnt = 0;     // monotonic across replays; no reset needed

// Dynamic smem layout for GEMM phase (float offsets) — R13-measured-best.
#define WS1_OFF 0                              // [64*128]          8192 floats
#define WS2_OFF 8192                           // [128*64]          8192 floats
#define AS_OFF  16384                          // [128 rows][64 k]  8192 floats
#define H1_OFF  24576                          // [128 rows][132]  16896 floats
#define SMEM_FLOATS (H1_OFF + GTILE * 132)     // 41472
#define SMEM_BYTES (SMEM_FLOATS * 4)           // 165888

// ---------------- helpers ----------------
__device__ __forceinline__ u64 pack_dup(float v) {
    u64 r; asm("mov.b64 %0, {%1,%1};" : "=l"(r) : "f"(v)); return r;
}
__device__ __forceinline__ void fma2(u64& d, u64 a, u64 b) {
    asm("fma.rn.f32x2 %0, %1, %2, %0;" : "+l"(d) : "l"(a), "l"(b));
}
__device__ __forceinline__ float2 unpack2(u64 v) {
    float2 r; asm("mov.b64 {%0,%1}, %2;" : "=f"(r.x), "=f"(r.y) : "l"(v)); return r;
}

// Monotonic grid barrier: instance g consumes arrivals [g*NBLK, (g+1)*NBLK).
__device__ __forceinline__ void grid_sync() {
    __syncthreads();
    if (threadIdx.x == 0) {
        __threadfence();
        unsigned my = atomicAdd(&g_barcnt, 1u);
        unsigned target = (my / NBLK + 1u) * NBLK;
        unsigned v;
        do {
            asm volatile("ld.volatile.global.u32 %0, [%1];" : "=r"(v) : "l"(&g_barcnt));
        } while (v < target);
        __threadfence();
    }
    __syncthreads();
}

__device__ __forceinline__ void acc_row(const float4* __restrict__ base4, int s, int c2,
                                        float4& a0, float4& a1) {
    const float4* p = base4 + (size_t)s * 16 + c2;
    float4 v0 = __ldg(p), v1 = __ldg(p + 1);
    a0.x += v0.x; a0.y += v0.y; a0.z += v0.z; a0.w += v0.w;
    a1.x += v1.x; a1.y += v1.y; a1.z += v1.z; a1.w += v1.w;
}

// ---------------- the mega-kernel ----------------
__global__ __launch_bounds__(NTHR) void gnn_mega_kernel(
    const float* __restrict__ h,
    const int*   __restrict__ src,
    const int*   __restrict__ dst,
    const float* __restrict__ W1,
    const float* __restrict__ b1,
    const float* __restrict__ W2,
    const float* __restrict__ b2,
    float*       __restrict__ out)
{
    extern __shared__ __align__(16) float sm[];
    int tid = threadIdx.x;
    int gt  = blockIdx.x * NTHR + tid;

    // ===== P0: zero degree counters =====
    for (int i = gt; i < N_NODES; i += TTOT) { g_deg_out[i] = 0; g_deg_in[i] = 0; }
    if (gt == 0) g_alloc = 0;
    grid_sync();

    // ===== P1: degrees (2 edges per step; rank = in-degree atomic return) =====
    for (int t = gt; t < N_EDGES / 2; t += TTOT) {
        int2 s = __ldg(reinterpret_cast<const int2*>(src) + t);
        int2 d = __ldg(reinterpret_cast<const int2*>(dst) + t);
        atomicAdd(&g_deg_out[s.x], 1);
        atomicAdd(&g_deg_out[s.y], 1);
        int2 r;
        r.x = atomicAdd(&g_deg_in[d.x], 1);
        r.y = atomicAdd(&g_deg_in[d.y], 1);
        reinterpret_cast<int2*>(g_rank)[t] = r;
    }
    grid_sync();

    // ===== P2: per-chunk scan (1024 nodes/block) + norms =====
    {
        int* si = reinterpret_cast<int*>(sm);        // [1024]
        __shared__ int base;
        int nchunks = (N_NODES + NTHR - 1) / NTHR;   // 49
        if (blockIdx.x < nchunks) {
            int i = blockIdx.x * NTHR + tid;
            int deg = 0, dout = 0;
            if (i < N_NODES) { deg = g_deg_in[i]; dout = g_deg_out[i]; }
            si[tid] = deg;
            __syncthreads();
#pragma unroll
            for (int o = 1; o < NTHR; o <<= 1) {
                int v = (tid >= o) ? si[tid - o] : 0;
                __syncthreads();
                si[tid] += v;
                __syncthreads();
            }
            if (tid == NTHR - 1) base = atomicAdd(&g_alloc, si[NTHR - 1]);
            __syncthreads();
            if (i < N_NODES) {
                g_off[i] = base + si[tid] - deg;
                g_norm_src[i] = rsqrtf(fmaxf((float)dout, 1.f));
                g_norm_dst[i] = rsqrtf(fmaxf((float)deg,  1.f));
            }
        }
    }
    grid_sync();

    // ===== P3: CSR fill (atomic-free) + prescale hs = h * norm_src =====
    for (int t = gt; t < N_EDGES / 2; t += TTOT) {
        int2 s = __ldg(reinterpret_cast<const int2*>(src) + t);
        int2 d = __ldg(reinterpret_cast<const int2*>(dst) + t);
        int2 r = *(reinterpret_cast<const int2*>(g_rank) + t);
        g_esrc[__ldg(&g_off[d.x]) + r.x] = s.x;
        g_esrc[__ldg(&g_off[d.y]) + r.y] = s.y;
    }
    for (int i = gt; i < N_NODES * F_IN / 4; i += TTOT) {
        float ns = __ldg(&g_norm_src[i >> 4]);
        float4 v = __ldg(reinterpret_cast<const float4*>(h) + i);
        v.x *= ns; v.y *= ns; v.z *= ns; v.w *= ns;
        reinterpret_cast<float4*>(g_hs)[i] = v;
    }
    grid_sync();

    // ===== P4: pull-aggregate layer 1 =====
    for (int t = gt; t < N_NODES * 8; t += TTOT) {
        int n  = t >> 3;
        int c2 = (t & 7) << 1;
        int i   = __ldg(&g_off[n]);
        int end = i + __ldg(&g_deg_in[n]);
        const float4* hs4 = reinterpret_cast<const float4*>(g_hs);
        float4 a0 = make_float4(0.f,0.f,0.f,0.f);
        float4 a1 = a0;
        while ((i & 3) && i < end) acc_row(hs4, __ldg(&g_esrc[i++]), c2, a0, a1);
        const int4* e4 = reinterpret_cast<const int4*>(g_esrc);
        for (; i + 4 <= end; i += 4) {
            int4 q = __ldg(&e4[i >> 2]);
            acc_row(hs4, q.x, c2, a0, a1);
            acc_row(hs4, q.y, c2, a0, a1);
            acc_row(hs4, q.z, c2, a0, a1);
            acc_row(hs4, q.w, c2, a0, a1);
        }
        for (; i < end; i++) acc_row(hs4, __ldg(&g_esrc[i]), c2, a0, a1);
        float4* o = reinterpret_cast<float4*>(g_agg1) + (size_t)n * 16 + c2;
        o[0] = a0; o[1] = a1;
    }
    grid_sync();

    // ===== P5: fused GEMM (R13-measured-best body) =====
    {
        float* Ws1 = sm + WS1_OFF;
        float* Ws2 = sm + WS2_OFF;
        float* As  = sm + AS_OFF;
        float* H1s = sm + H1_OFF;

        for (int i = tid; i < F_IN * F_MID / 4; i += NTHR)
            reinterpret_cast<float4*>(Ws1)[i] = __ldg(reinterpret_cast<const float4*>(W1) + i);
        for (int i = tid; i < F_MID * F_IN / 4; i += NTHR)
            reinterpret_cast<float4*>(Ws2)[i] = __ldg(reinterpret_cast<const float4*>(W2) + i);

        int ct = tid & 31;
        int rt = tid >> 5;
        int ct2 = tid & 15;
        int rt2 = tid >> 4;
        float4 bb = __ldg(reinterpret_cast<const float4*>(b1) + ct);

        for (int tile = blockIdx.x; tile < NTILES; tile += NBLK) {
            int row0 = tile * GTILE;
            __syncthreads();
            for (int i = tid; i < GTILE * F_IN / 4; i += NTHR) {
                int r  = i >> 4;
                int c4 = i & 15;
                int row = row0 + r;
                float4 v = (row < N_NODES)
                    ? *reinterpret_cast<const float4*>(g_agg1 + (size_t)row * F_IN + (c4 << 2))
                    : make_float4(0.f, 0.f, 0.f, 0.f);
                *reinterpret_cast<float4*>(&As[r * F_IN + (c4 << 2)]) = v;
            }
            __syncthreads();

            u64 acc[4][2];
#pragma unroll
            for (int j = 0; j < 4; j++) { acc[j][0] = 0ull; acc[j][1] = 0ull; }
            int rbase = rt << 2;
#pragma unroll 4
            for (int k4 = 0; k4 < F_IN / 4; k4++) {
                float4 a0 = *reinterpret_cast<const float4*>(&As[(rbase + 0) * F_IN + (k4 << 2)]);
                float4 a1 = *reinterpret_cast<const float4*>(&As[(rbase + 1) * F_IN + (k4 << 2)]);
                float4 a2 = *reinterpret_cast<const float4*>(&As[(rbase + 2) * F_IN + (k4 << 2)]);
                float4 a3 = *reinterpret_cast<const float4*>(&As[(rbase + 3) * F_IN + (k4 << 2)]);
#pragma unroll
                for (int kk = 0; kk < 4; kk++) {
                    ulonglong2 w = *reinterpret_cast<const ulonglong2*>(
                        &Ws1[((k4 << 2) + kk) * F_MID + (ct << 2)]);
                    float av0 = kk == 0 ? a0.x : kk == 1 ? a0.y : kk == 2 ? a0.z : a0.w;
                    float av1 = kk == 0 ? a1.x : kk == 1 ? a1.y : kk == 2 ? a1.z : a1.w;
                    float av2 = kk == 0 ? a2.x : kk == 1 ? a2.y : kk == 2 ? a2.z : a2.w;
                    float av3 = kk == 0 ? a3.x : kk == 1 ? a3.y : kk == 2 ? a3.z : a3.w;
                    u64 p0 = pack_dup(av0), p1 = pack_dup(av1);
                    u64 p2 = pack_dup(av2), p3 = pack_dup(av3);
                    fma2(acc[0][0], p0, w.x); fma2(acc[0][1], p0, w.y);
                    fma2(acc[1][0], p1, w.x); fma2(acc[1][1], p1, w.y);
                    fma2(acc[2][0], p2, w.x); fma2(acc[2][1], p2, w.y);
                    fma2(acc[3][0], p3, w.x); fma2(acc[3][1], p3, w.y);
                }
            }
#pragma unroll
            for (int j = 0; j < 4; j++) {
                int lr = rbase + j;
                int row = row0 + lr;
                float nd = (row < N_NODES) ? __ldg(&g_norm_dst[row]) : 0.f;
                float2 u0 = unpack2(acc[j][0]);
                float2 u1 = unpack2(acc[j][1]);
                float4 o;
                o.x = fmaxf(fmaf(u0.x, nd, bb.x), 0.f);
                o.y = fmaxf(fmaf(u0.y, nd, bb.y), 0.f);
                o.z = fmaxf(fmaf(u1.x, nd, bb.z), 0.f);
                o.w = fmaxf(fmaf(u1.y, nd, bb.w), 0.f);
                *reinterpret_cast<float4*>(&H1s[lr * 132 + (ct << 2)]) = o;
            }
            __syncthreads();

            u64 acc2[2][2];
            acc2[0][0] = acc2[0][1] = acc2[1][0] = acc2[1][1] = 0ull;
            int r0 = rt2 << 1;
#pragma unroll 4
            for (int k4 = 0; k4 < F_MID / 4; k4++) {
                float4 a0v = *reinterpret_cast<const float4*>(&H1s[r0 * 132 + (k4 << 2)]);
                float4 a1v = *reinterpret_cast<const float4*>(&H1s[(r0 + 1) * 132 + (k4 << 2)]);
#pragma unroll
                for (int kk = 0; kk < 4; kk++) {
                    ulonglong2 w = *reinterpret_cast<const ulonglong2*>(
                        &Ws2[((k4 << 2) + kk) * F_IN + (ct2 << 2)]);
                    float av0 = kk == 0 ? a0v.x : kk == 1 ? a0v.y : kk == 2 ? a0v.z : a0v.w;
                    float av1 = kk == 0 ? a1v.x : kk == 1 ? a1v.y : kk == 2 ? a1v.z : a1v.w;
                    u64 p0 = pack_dup(av0), p1 = pack_dup(av1);
                    fma2(acc2[0][0], p0, w.x); fma2(acc2[0][1], p0, w.y);
                    fma2(acc2[1][0], p1, w.x); fma2(acc2[1][1], p1, w.y);
                }
            }
#pragma unroll
            for (int j = 0; j < 2; j++) {
                int row = row0 + r0 + j;
                if (row < N_NODES) {
                    float ns = __ldg(&g_norm_src[row]);
                    float2 u0 = unpack2(acc2[j][0]);
                    float2 u1 = unpack2(acc2[j][1]);
                    float4 o;
                    o.x = u0.x * ns; o.y = u0.y * ns;
                    o.z = u1.x * ns; o.w = u1.y * ns;
                    *reinterpret_cast<float4*>(g_t2 + (size_t)row * F_IN + (ct2 << 2)) = o;
                }
            }
        }
    }
    grid_sync();

    // ===== P6: pull-aggregate layer 2 + epilogue =====
    for (int t = gt; t < N_NODES * 8; t += TTOT) {
        int n  = t >> 3;
        int c2 = (t & 7) << 1;
        int i   = __ldg(&g_off[n]);
        int end = i + __ldg(&g_deg_in[n]);
        const float4* t4 = reinterpret_cast<const float4*>(g_t2);
        float4 a0 = make_float4(0.f,0.f,0.f,0.f);
        float4 a1 = a0;
        while ((i & 3) && i < end) acc_row(t4, __ldg(&g_esrc[i++]), c2, a0, a1);
        const int4* e4 = reinterpret_cast<const int4*>(g_esrc);
        for (; i + 4 <= end; i += 4) {
            int4 q = __ldg(&e4[i >> 2]);
            acc_row(t4, q.x, c2, a0, a1);
            acc_row(t4, q.y, c2, a0, a1);
            acc_row(t4, q.z, c2, a0, a1);
            acc_row(t4, q.w, c2, a0, a1);
        }
        for (; i < end; i++) acc_row(t4, __ldg(&g_esrc[i]), c2, a0, a1);

        float nd = __ldg(&g_norm_dst[n]);
        float4 b0 = __ldg(reinterpret_cast<const float4*>(b2) + c2);
        float4 b1v = __ldg(reinterpret_cast<const float4*>(b2) + c2 + 1);
        float4 o0, o1;
        o0.x = fmaf(a0.x, nd, b0.x);  o0.y = fmaf(a0.y, nd, b0.y);
        o0.z = fmaf(a0.z, nd, b0.z);  o0.w = fmaf(a0.w, nd, b0.w);
        o1.x = fmaf(a1.x, nd, b1v.x); o1.y = fmaf(a1.y, nd, b1v.y);
        o1.z = fmaf(a1.z, nd, b1v.z); o1.w = fmaf(a1.w, nd, b1v.w);
        float4* o = reinterpret_cast<float4*>(out) + (size_t)n * 16 + c2;
        o[0] = o0; o[1] = o1;
    }
}

// ---------------- launch ----------------
extern "C" void kernel_launch(void* const* d_in, const int* in_sizes, int n_in,
                              void* d_out, int out_size) {
    const float* h   = (const float*)d_in[0];
    const int*   src = (const int*)  d_in[1];
    const int*   dst = (const int*)  d_in[2];
    const float* W1  = (const float*)d_in[3];
    const float* b1  = (const float*)d_in[4];
    const float* W2  = (const float*)d_in[5];
    const float* b2  = (const float*)d_in[6];
    float* out = (float*)d_out;

    cudaFuncSetAttribute(gnn_mega_kernel,
                         cudaFuncAttributeMaxDynamicSharedMemorySize, SMEM_BYTES);

    gnn_mega_kernel<<<NBLK, NTHR, SMEM_BYTES>>>(h, src, dst, W1, b1, W2, b2, out);
}